// round 12
// baseline (speedup 1.0000x reference)
#include <cuda_runtime.h>
#include <math_constants.h>

// Fixed shapes
#define BB   8
#define NN   8192
#define SS   2048
#define DD   256
#define QB   128           // queries per block
#define NPART 4            // S split 4 ways
#define TPB  (QB * NPART)  // 512 threads
#define SPT  (SS / NPART)  // 512 points per thread
#define EPSF 1e-8f

// Insert (t,s) into ascending top-3 (d0<=d1<=d2). Strict '<' keeps earlier
// (lower-index) entries on ties, matching top_k's first-occurrence rule.
#define INSERT3(t, s)                                                   \
    if ((t) < d2) {                                                     \
        if ((t) < d1) {                                                 \
            d2 = d1; i2 = i1;                                           \
            if ((t) < d0) { d1 = d0; i1 = i0; d0 = (t); i0 = (s); }     \
            else          { d1 = (t); i1 = (s); }                       \
        } else { d2 = (t); i2 = (s); }                                  \
    }

struct MergeScratch {
    float d[NPART - 1][QB][3];
    int   i[NPART - 1][QB][3];
};

__global__ __launch_bounds__(TPB, 3)
void fp_interp_kernel(const float* __restrict__ xyz1,     // [B,3,N]
                      const float* __restrict__ xyz2,     // [B,3,S]
                      const float* __restrict__ points2,  // [B,S,D]
                      float* __restrict__ out)            // [B,N,D]
{
    // sxyz is dead after the scan; merge scratch overlays it.
    __shared__ union SU {
        float4 sxyz[SS];           // 32 KB: (x, y, z, |p|^2)
        MergeScratch mrg;          // 9 KB, used after scan
    } U;
    __shared__ float swgt[QB][3];
    __shared__ int   sidx[QB][3];

    const int tile = blockIdx.x;   // 0..511 (64 tiles per batch)
    const int b    = tile >> 6;
    const int n0   = (tile & 63) * QB;
    const int tid  = threadIdx.x;

    // --- stage xyz2[b] into shared with precomputed |p|^2 ---
    const float* x2b = xyz2 + (size_t)b * 3 * SS;
    #pragma unroll
    for (int s = tid; s < SS; s += TPB) {
        const float x = x2b[s], y = x2b[SS + s], z = x2b[2 * SS + s];
        U.sxyz[s] = make_float4(x, y, z, fmaf(x, x, fmaf(y, y, z * z)));
    }
    __syncthreads();

    // --- phase 1: 4-way split top-3 scan; t = |p|^2 - 2 q.p (same order as d) ---
    const int q    = tid & (QB - 1);
    const int part = tid >> 7;      // 0..3 (uniform per warp)
    const int n    = n0 + q;
    const float* x1b = xyz1 + (size_t)b * 3 * NN;
    const float qx = x1b[n], qy = x1b[NN + n], qz = x1b[2 * NN + n];
    const float ax = -2.0f * qx, ay = -2.0f * qy, az = -2.0f * qz;
    const float qq = fmaf(qx, qx, fmaf(qy, qy, qz * qz));

    float d0 = CUDART_MAX_NORMAL_F, d1 = CUDART_MAX_NORMAL_F, d2 = CUDART_MAX_NORMAL_F;
    int   i0 = 0, i1 = 0, i2 = 0;

    const int sbeg = part * SPT;
    #pragma unroll 2
    for (int s = sbeg; s < sbeg + SPT; s += 4) {
        const float4 p0 = U.sxyz[s];
        const float4 p1 = U.sxyz[s + 1];
        const float4 p2 = U.sxyz[s + 2];
        const float4 p3 = U.sxyz[s + 3];
        const float t0 = fmaf(p0.x, ax, fmaf(p0.y, ay, fmaf(p0.z, az, p0.w)));
        const float t1 = fmaf(p1.x, ax, fmaf(p1.y, ay, fmaf(p1.z, az, p1.w)));
        const float t2 = fmaf(p2.x, ax, fmaf(p2.y, ay, fmaf(p2.z, az, p2.w)));
        const float t3 = fmaf(p3.x, ax, fmaf(p3.y, ay, fmaf(p3.z, az, p3.w)));
        const float m  = fminf(fminf(t0, t1), fminf(t2, t3));
        if (m < d2) {                      // rare path
            INSERT3(t0, s)
            INSERT3(t1, s + 1)
            INSERT3(t2, s + 2)
            INSERT3(t3, s + 3)
        }
    }

    // --- merge the 4 partial triples (parts 1..3 publish; part 0 merges) ---
    __syncthreads();                 // sxyz reads done; safe to overlay
    if (part) {
        U.mrg.d[part - 1][q][0] = d0; U.mrg.d[part - 1][q][1] = d1; U.mrg.d[part - 1][q][2] = d2;
        U.mrg.i[part - 1][q][0] = i0; U.mrg.i[part - 1][q][1] = i1; U.mrg.i[part - 1][q][2] = i2;
    }
    __syncthreads();
    if (!part) {
        #pragma unroll
        for (int p = 0; p < NPART - 1; ++p) {
            #pragma unroll
            for (int k = 0; k < 3; ++k) {
                const float t = U.mrg.d[p][q][k];
                const int   s = U.mrg.i[p][q][k];
                INSERT3(t, s)
            }
        }
        // true squared distances and inverse-distance weights
        const float r0 = 1.0f / ((d0 + qq) + EPSF);
        const float r1 = 1.0f / ((d1 + qq) + EPSF);
        const float r2 = 1.0f / ((d2 + qq) + EPSF);
        const float inv = 1.0f / (r0 + r1 + r2);
        sidx[q][0] = i0; sidx[q][1] = i1; sidx[q][2] = i2;
        swgt[q][0] = r0 * inv; swgt[q][1] = r1 * inv; swgt[q][2] = r2 * inv;
    }
    __syncthreads();

    // --- phase 2: cooperative gather + weighted sum, coalesced float4 ---
    const int warp = tid >> 5;      // 0..15
    const int lane = tid & 31;
    const float4* p2f = (const float4*)(points2 + (size_t)b * SS * DD); // rows of 64 float4
    float4* ob = (float4*)(out + ((size_t)b * NN + n0) * DD);

    #pragma unroll
    for (int qi = warp; qi < QB; qi += TPB / 32) {
        const int j0 = sidx[qi][0] * (DD / 4);
        const int j1 = sidx[qi][1] * (DD / 4);
        const int j2 = sidx[qi][2] * (DD / 4);
        const float w0 = swgt[qi][0];
        const float w1 = swgt[qi][1];
        const float w2 = swgt[qi][2];
        float4* oq = ob + (size_t)qi * (DD / 4);
        #pragma unroll
        for (int j = lane; j < DD / 4; j += 32) {
            const float4 a = p2f[j0 + j];
            const float4 c = p2f[j1 + j];
            const float4 e = p2f[j2 + j];
            float4 r;
            r.x = w0 * a.x + w1 * c.x + w2 * e.x;
            r.y = w0 * a.y + w1 * c.y + w2 * e.y;
            r.z = w0 * a.z + w1 * c.z + w2 * e.z;
            r.w = w0 * a.w + w1 * c.w + w2 * e.w;
            oq[j] = r;
        }
    }
}

extern "C" void kernel_launch(void* const* d_in, const int* in_sizes, int n_in,
                              void* d_out, int out_size)
{
    // inputs: xyz1 [B,3,N], xyz2 [B,3,S], points1 [B,D,N] (unused), points2 [B,S,D]
    const float* xyz1    = (const float*)d_in[0];
    const float* xyz2    = (const float*)d_in[1];
    const float* points2 = (const float*)d_in[3];
    float* out = (float*)d_out;

    const int blocks = BB * (NN / QB);   // 8 * 64 = 512
    fp_interp_kernel<<<blocks, TPB>>>(xyz1, xyz2, points2, out);
}